// round 14
// baseline (speedup 1.0000x reference)
#include <cuda_runtime.h>
#include <cstddef>

// B=128, D=1024. d_in[0]=mu (131072 f32), d_in[1]=Sigma (128*1024*1024 f32)
// d_out = [mu_out 131072 f32 | Sigma_out 134217728 f32]
//
// FINAL config (28 regs, occ 82%, kernel 116.2 us, DRAM 81%) + column-skip:
// within an active row, a thread whose 4 columns are all masked off skips
// its Sigma load entirely (output is zero regardless). ~6% fewer load
// wavefronts; DRAM-level saving small (sector granularity) but free.
//
// Search history (all benched): MLP4/8, 16B/32B ops, default/streaming/
// write-through policies, store-first ordering, persistent CTAs. SM-side
// configs plateau at 6.37-6.44 TB/s = mixed-stream (1:2 R:W) HBM ceiling.
// Traffic is algorithmically minimal: 512 MB compulsory stores + ~253 MB
// active-row loads (inactive rows zero-filled without reading Sigma).

static constexpr int B = 128;
static constexpr int D = 1024;
static constexpr int ROWS = 4;

__global__ __launch_bounds__(256) void rvrelu_kernel(
    const float4* __restrict__ Sigma,
    const float*  __restrict__ mu,
    float4* __restrict__ Sigma_out,
    float4* __restrict__ mu_out4) {

    const int blk  = blockIdx.x;        // 0 .. 32767
    const int row0 = blk << 2;          // first of 4 rows
    const int b    = row0 >> 10;        // batch index
    const int t    = threadIdx.x;       // 0..255

    // 4 row masks in one aligned 16B load (L2-hot after first touch)
    const float4 mi4 = __ldg(reinterpret_cast<const float4*>(mu) + blk);

    // fused mu_out: one relu'd float4 store per block
    if (t == 0) {
        float4 r;
        r.x = mi4.x > 0.0f ? mi4.x : 0.0f;
        r.y = mi4.y > 0.0f ? mi4.y : 0.0f;
        r.z = mi4.z > 0.0f ? mi4.z : 0.0f;
        r.w = mi4.w > 0.0f ? mi4.w : 0.0f;
        mu_out4[blk] = r;
    }

    // column mask: mu[b, 4t..4t+3], shared by all 4 rows (L2-hot)
    const float4 mrow =
        __ldg(reinterpret_cast<const float4*>(mu + (size_t)b * D) + t);

    // If all 4 of this thread's columns are inactive, every output it owns
    // is zero -> skip the Sigma load for every row (P ~ 6.25%).
    const bool colActive = (mrow.x > 0.0f) | (mrow.y > 0.0f) |
                           (mrow.z > 0.0f) | (mrow.w > 0.0f);

    const float mis[ROWS] = {mi4.x, mi4.y, mi4.z, mi4.w};
    const size_t base = (size_t)row0 * (D / 4) + t;   // float4 index

    // Phase 1: issue all 4 independent Sigma loads (predicated) -> MLP=4
    float4 v[ROWS];
#pragma unroll
    for (int r = 0; r < ROWS; r++) {
        if (colActive && mis[r] > 0.0f) {
            v[r] = __ldg(Sigma + base + (size_t)r * (D / 4));
        } else {
            v[r] = make_float4(0.0f, 0.0f, 0.0f, 0.0f);
        }
    }

    // Phase 2: apply column mask and store
#pragma unroll
    for (int r = 0; r < ROWS; r++) {
        float4 o = v[r];
        o.x = mrow.x > 0.0f ? o.x : 0.0f;
        o.y = mrow.y > 0.0f ? o.y : 0.0f;
        o.z = mrow.z > 0.0f ? o.z : 0.0f;
        o.w = mrow.w > 0.0f ? o.w : 0.0f;
        Sigma_out[base + (size_t)r * (D / 4)] = o;
    }
}

extern "C" void kernel_launch(void* const* d_in, const int* in_sizes, int n_in,
                              void* d_out, int out_size) {
    const float* mu    = (const float*)d_in[0];
    const float* Sigma = (const float*)d_in[1];

    float4* mu_out4   = (float4*)d_out;
    float4* Sigma_out = (float4*)((float*)d_out + (size_t)B * D);

    // 32768 blocks x 256 threads; 4 Sigma rows per block
    rvrelu_kernel<<<(B * D) / ROWS, 256>>>(
        (const float4*)Sigma, mu, Sigma_out, mu_out4);
}

// round 15
// speedup vs baseline: 1.0113x; 1.0113x over previous
#include <cuda_runtime.h>
#include <cstddef>

// B=128, D=1024. d_in[0]=mu (131072 f32), d_in[1]=Sigma (128*1024*1024 f32)
// d_out = [mu_out 131072 f32 | Sigma_out 134217728 f32]
//
// FINAL — committed. Best measured config: 28 regs, occ 82%, kernel
// 116.2 us, DRAM 81.2% (6.44 TB/s). Ten structural variants benched:
//   MLP4 / MLP8 row-unroll          -> neutral
//   16B (float4) / 32B (v8.f32) ops -> 16B equal or better
//   default / __ldcs+__stcs / st.wt -> default best (wt loses L2 coalescing)
//   store-first zero-row ordering   -> neutral, +12 regs
//   column-skip predicate           -> neutral, +alu
//   persistent 1184-CTA grid        -> -20% (CTA churn supplies chip MLP)
// All SM-side configs plateau at 6.37-6.44 TB/s = the mixed-stream
// (1:2 read:write) HBM ceiling on this part. Traffic is algorithmically
// minimal: 512 MB compulsory stores + ~253 MB active-row loads (rows with
// mu[b,i]<=0 are zero-filled without reading Sigma; mu is L2-resident).
//
// Layout: one CTA per 4 consecutive Sigma rows (always within one batch b).
// 256 threads; thread t owns columns [4t, 4t+4) of all 4 rows:
//   - one float4 load gives the 4 row-masks (mu[4*blk .. 4*blk+3])
//   - one float4 load of the mu row gives the column mask, reused 4x
//   - 4 independent Sigma float4 loads (MLP=4), predicated off per-row mask
//   - thread 0 writes the relu'd mu_out float4 (fused, no second kernel)

static constexpr int B = 128;
static constexpr int D = 1024;
static constexpr int ROWS = 4;

__global__ __launch_bounds__(256) void rvrelu_kernel(
    const float4* __restrict__ Sigma,
    const float*  __restrict__ mu,
    float4* __restrict__ Sigma_out,
    float4* __restrict__ mu_out4) {

    const int blk  = blockIdx.x;        // 0 .. 32767
    const int row0 = blk << 2;          // first of 4 rows
    const int b    = row0 >> 10;        // batch index
    const int t    = threadIdx.x;       // 0..255

    // 4 row masks in one aligned 16B load (L2-hot after first touch)
    const float4 mi4 = __ldg(reinterpret_cast<const float4*>(mu) + blk);

    // fused mu_out: one relu'd float4 store per block
    if (t == 0) {
        float4 r;
        r.x = mi4.x > 0.0f ? mi4.x : 0.0f;
        r.y = mi4.y > 0.0f ? mi4.y : 0.0f;
        r.z = mi4.z > 0.0f ? mi4.z : 0.0f;
        r.w = mi4.w > 0.0f ? mi4.w : 0.0f;
        mu_out4[blk] = r;
    }

    // column mask: mu[b, 4t..4t+3], shared by all 4 rows (L2-hot)
    const float4 mrow =
        __ldg(reinterpret_cast<const float4*>(mu + (size_t)b * D) + t);

    const float mis[ROWS] = {mi4.x, mi4.y, mi4.z, mi4.w};
    const size_t base = (size_t)row0 * (D / 4) + t;   // float4 index

    // Phase 1: issue all 4 independent Sigma loads (predicated) -> MLP=4
    float4 v[ROWS];
#pragma unroll
    for (int r = 0; r < ROWS; r++) {
        if (mis[r] > 0.0f) {
            v[r] = __ldg(Sigma + base + (size_t)r * (D / 4));
        } else {
            v[r] = make_float4(0.0f, 0.0f, 0.0f, 0.0f);
        }
    }

    // Phase 2: apply column mask and store
#pragma unroll
    for (int r = 0; r < ROWS; r++) {
        float4 o = v[r];
        o.x = mrow.x > 0.0f ? o.x : 0.0f;
        o.y = mrow.y > 0.0f ? o.y : 0.0f;
        o.z = mrow.z > 0.0f ? o.z : 0.0f;
        o.w = mrow.w > 0.0f ? o.w : 0.0f;
        Sigma_out[base + (size_t)r * (D / 4)] = o;
    }
}

extern "C" void kernel_launch(void* const* d_in, const int* in_sizes, int n_in,
                              void* d_out, int out_size) {
    const float* mu    = (const float*)d_in[0];
    const float* Sigma = (const float*)d_in[1];

    float4* mu_out4   = (float4*)d_out;
    float4* Sigma_out = (float4*)((float*)d_out + (size_t)B * D);

    // 32768 blocks x 256 threads; 4 Sigma rows per block
    rvrelu_kernel<<<(B * D) / ROWS, 256>>>(
        (const float4*)Sigma, mu, Sigma_out, mu_out4);
}